// round 2
// baseline (speedup 1.0000x reference)
#include <cuda_runtime.h>
#include <cuda_bf16.h>
#include <mma.h>

using namespace nvcuda;

// Problem constants
#define BB 2
#define SS 2048
#define DD 512
#define HH 8
#define HDIM 64
#define KROUTE 64

// ---------------------------------------------------------------------------
// Scratch (device globals; no allocation allowed)
// ---------------------------------------------------------------------------
__device__ float g_q[BB * HH * SS * HDIM];
__device__ float g_k[BB * HH * SS * HDIM];
__device__ float g_v[BB * HH * SS * HDIM];

__device__ __nv_bfloat16 gx_hi[BB * SS * DD];
__device__ __nv_bfloat16 gx_lo[BB * SS * DD];
__device__ __nv_bfloat16 gw1_hi[DD * 3 * DD];
__device__ __nv_bfloat16 gw1_lo[DD * 3 * DD];
__device__ __nv_bfloat16 gw2_hi[DD * DD];
__device__ __nv_bfloat16 gw2_lo[DD * DD];
__device__ __nv_bfloat16 gat_hi[BB * SS * DD];
__device__ __nv_bfloat16 gat_lo[BB * SS * DD];

// ---------------------------------------------------------------------------
// fp32 -> bf16 hi/lo split conversion (vectorized float4)
// ---------------------------------------------------------------------------
__global__ __launch_bounds__(256) void cvt_k(
    const float4* __restrict__ src,
    __nv_bfloat162* __restrict__ hi,
    __nv_bfloat162* __restrict__ lo, int n4)
{
    int i = blockIdx.x * 256 + threadIdx.x;
    if (i >= n4) return;
    float4 v = src[i];
    __nv_bfloat16 h0 = __float2bfloat16(v.x);
    __nv_bfloat16 h1 = __float2bfloat16(v.y);
    __nv_bfloat16 h2 = __float2bfloat16(v.z);
    __nv_bfloat16 h3 = __float2bfloat16(v.w);
    hi[2 * i + 0] = __halves2bfloat162(h0, h1);
    hi[2 * i + 1] = __halves2bfloat162(h2, h3);
    __nv_bfloat16 l0 = __float2bfloat16(v.x - __bfloat162float(h0));
    __nv_bfloat16 l1 = __float2bfloat16(v.y - __bfloat162float(h1));
    __nv_bfloat16 l2 = __float2bfloat16(v.z - __bfloat162float(h2));
    __nv_bfloat16 l3 = __float2bfloat16(v.w - __bfloat162float(h3));
    lo[2 * i + 0] = __halves2bfloat162(l0, l1);
    lo[2 * i + 1] = __halves2bfloat162(l2, l3);
}

// ---------------------------------------------------------------------------
// Tensor-core GEMM, bf16 hi/lo x3 split (near-fp32 accuracy), 128x128x32 tile.
//   C = (Ahi+Alo) @ (Bhi+Blo) + bias  (lo*lo term dropped)
//   MODE 0: dense store to C [M,N]
//   MODE 1: scatter into g_q/g_k/g_v with head reshuffle
// 8 warps: 4 (m) x 2 (n); warp tile 32x64 = 2x4 wmma 16x16x16 frags.
// ---------------------------------------------------------------------------
template <int MODE>
__global__ __launch_bounds__(256) void gemm_bf16(
    const __nv_bfloat16* __restrict__ Ahi, const __nv_bfloat16* __restrict__ Alo,
    const __nv_bfloat16* __restrict__ Bhi, const __nv_bfloat16* __restrict__ Blo,
    const float* __restrict__ bias, float* __restrict__ C,
    int M, int N, int Kd)
{
    extern __shared__ __align__(16) char smem[];
    constexpr int BM = 128, BN = 128, BK = 32;
    constexpr int LDA = BK + 8;   // 40 bf16
    constexpr int LDB = BN + 8;   // 136 bf16
    constexpr int LDS_ = BN + 4;  // 132 floats for staging

    __nv_bfloat16* sAh = (__nv_bfloat16*)smem;
    __nv_bfloat16* sAl = sAh + BM * LDA;
    __nv_bfloat16* sBh = sAl + BM * LDA;
    __nv_bfloat16* sBl = sBh + BK * LDB;
    float* stage = (float*)smem;  // union: reused after the k-loop

    const int tid = threadIdx.x;
    const int wid = tid >> 5;
    const int wm = wid & 3;   // m warp coord
    const int wn = wid >> 2;  // n warp coord

    wmma::fragment<wmma::accumulator, 16, 16, 16, float> acc[2][4];
    #pragma unroll
    for (int mi = 0; mi < 2; mi++)
        #pragma unroll
        for (int ni = 0; ni < 4; ni++) wmma::fill_fragment(acc[mi][ni], 0.0f);

    const size_t aBase = (size_t)blockIdx.y * BM * Kd;
    const int nBase = blockIdx.x * BN;

    for (int k0 = 0; k0 < Kd; k0 += BK) {
        // Load tiles: A 128x32 (512 x 16B chunks), B 32x128 (512 chunks)
        #pragma unroll
        for (int i = 0; i < 2; i++) {
            const int c = tid + 256 * i;
            const int ar = c >> 2, ac = (c & 3) * 8;
            const size_t aoff = aBase + (size_t)ar * Kd + k0 + ac;
            *(uint4*)&sAh[ar * LDA + ac] = *(const uint4*)&Ahi[aoff];
            *(uint4*)&sAl[ar * LDA + ac] = *(const uint4*)&Alo[aoff];
            const int br = c >> 4, bc = (c & 15) * 8;
            const size_t boff = (size_t)(k0 + br) * N + nBase + bc;
            *(uint4*)&sBh[br * LDB + bc] = *(const uint4*)&Bhi[boff];
            *(uint4*)&sBl[br * LDB + bc] = *(const uint4*)&Blo[boff];
        }
        __syncthreads();

        #pragma unroll
        for (int kk = 0; kk < BK; kk += 16) {
            wmma::fragment<wmma::matrix_a, 16, 16, 16, __nv_bfloat16, wmma::row_major> ah[2], al[2];
            #pragma unroll
            for (int mi = 0; mi < 2; mi++) {
                wmma::load_matrix_sync(ah[mi], sAh + (wm * 32 + mi * 16) * LDA + kk, LDA);
                wmma::load_matrix_sync(al[mi], sAl + (wm * 32 + mi * 16) * LDA + kk, LDA);
            }
            #pragma unroll
            for (int ni = 0; ni < 4; ni++) {
                wmma::fragment<wmma::matrix_b, 16, 16, 16, __nv_bfloat16, wmma::row_major> bh, bl;
                wmma::load_matrix_sync(bh, sBh + kk * LDB + wn * 64 + ni * 16, LDB);
                wmma::load_matrix_sync(bl, sBl + kk * LDB + wn * 64 + ni * 16, LDB);
                #pragma unroll
                for (int mi = 0; mi < 2; mi++) {
                    wmma::mma_sync(acc[mi][ni], ah[mi], bh, acc[mi][ni]);
                    wmma::mma_sync(acc[mi][ni], ah[mi], bl, acc[mi][ni]);
                    wmma::mma_sync(acc[mi][ni], al[mi], bh, acc[mi][ni]);
                }
            }
        }
        __syncthreads();
    }

    // Stage accumulators to smem, then epilogue with bias (+ optional scatter)
    #pragma unroll
    for (int mi = 0; mi < 2; mi++)
        #pragma unroll
        for (int ni = 0; ni < 4; ni++)
            wmma::store_matrix_sync(stage + (wm * 32 + mi * 16) * LDS_ + wn * 64 + ni * 16,
                                    acc[mi][ni], LDS_, wmma::mem_row_major);
    __syncthreads();

    #pragma unroll 4
    for (int i = 0; i < (BM * BN) / 256; i++) {
        const int flat = i * 256 + tid;
        const int r = flat >> 7;         // 0..127
        const int c = flat & 127;
        const int n = nBase + c;
        const float v = stage[r * LDS_ + c] + __ldg(&bias[n]);
        const int m = blockIdx.y * BM + r;
        if (MODE == 0) {
            C[(size_t)m * N + n] = v;
        } else {
            const int b = m >> 11;
            const int s = m & 2047;
            const int c3 = n >> 9;         // 0:q 1:k 2:v
            const int h = (n >> 6) & 7;
            const int d = n & 63;
            float* dst = (c3 == 0) ? g_q : (c3 == 1) ? g_k : g_v;
            dst[(((size_t)b * HH + h) * SS + s) * HDIM + d] = v;
        }
    }
}

// ---------------------------------------------------------------------------
// Routed attention. One warp per query; 32 consecutive s per CTA per (b,h).
// Score phase: lane l owns routes l and l+32 and computes FULL 64-dim dot
// products (q in registers, K rows gathered via independent LDG.128s) —
// no dependent shuffle chains. AV phase: broadcast scheme (independent shfls).
// Output written directly as bf16 hi/lo in [b, s, h*64+d] layout (A matrix of
// the out-projection GEMM).
// ---------------------------------------------------------------------------
__global__ __launch_bounds__(256) void attn_k(const int* __restrict__ routes)
{
    __shared__ float sq[8][64];
    const int lane = threadIdx.x & 31;
    const int warp = threadIdx.x >> 5;
    const int chunks = SS / 32;                  // 64
    const int bh = blockIdx.x / chunks;          // b*H + h
    const int sc = blockIdx.x % chunks;
    const int b = bh >> 3, h = bh & 7;

    const float* Qb = g_q + (size_t)bh * SS * HDIM;
    const float* Kb = g_k + (size_t)bh * SS * HDIM;
    const float* Vb = g_v + (size_t)bh * SS * HDIM;

    #pragma unroll 1
    for (int qi = 0; qi < 4; qi++) {
        const int s = sc * 32 + warp * 4 + qi;

        // q -> smem -> registers (broadcast reads, conflict-free)
        *(float2*)&sq[warp][lane * 2] = *(const float2*)(Qb + (size_t)s * HDIM + lane * 2);
        __syncwarp();
        float4 qr[16];
        #pragma unroll
        for (int j = 0; j < 16; j++) qr[j] = *(const float4*)&sq[warp][j * 4];
        __syncwarp();

        const int r_lo = routes[s * KROUTE + lane];
        const int r_hi = routes[s * KROUTE + 32 + lane];

        // Full dot products: 32 independent LDG.128s per lane, no shfl chains
        const float4* Klo = (const float4*)(Kb + (size_t)r_lo * HDIM);
        const float4* Khi = (const float4*)(Kb + (size_t)r_hi * HDIM);
        float slo = 0.f, shi = 0.f;
        #pragma unroll
        for (int j = 0; j < 16; j++) {
            const float4 a = Klo[j];
            slo = fmaf(a.x, qr[j].x, slo);
            slo = fmaf(a.y, qr[j].y, slo);
            slo = fmaf(a.z, qr[j].z, slo);
            slo = fmaf(a.w, qr[j].w, slo);
            const float4 c = Khi[j];
            shi = fmaf(c.x, qr[j].x, shi);
            shi = fmaf(c.y, qr[j].y, shi);
            shi = fmaf(c.z, qr[j].z, shi);
            shi = fmaf(c.w, qr[j].w, shi);
        }
        slo *= 0.125f;
        shi *= 0.125f;

        // Softmax over the 64 scores held 2-per-lane
        float mx = fmaxf(slo, shi);
        #pragma unroll
        for (int o = 16; o; o >>= 1) mx = fmaxf(mx, __shfl_xor_sync(0xffffffffu, mx, o));
        const float e_lo = __expf(slo - mx);
        const float e_hi = __expf(shi - mx);
        float sum = e_lo + e_hi;
        #pragma unroll
        for (int o = 16; o; o >>= 1) sum += __shfl_xor_sync(0xffffffffu, sum, o);
        const float inv = __fdividef(1.f, sum);
        const float w_lo = e_lo * inv, w_hi = e_hi * inv;

        // AV: broadcast route+weight per kk (independent shfls), lane owns 2 dims
        float2 acc = make_float2(0.f, 0.f);
        #pragma unroll 8
        for (int kk = 0; kk < 32; kk++) {
            const int r = __shfl_sync(0xffffffffu, r_lo, kk);
            const float w = __shfl_sync(0xffffffffu, w_lo, kk);
            const float2 vv = *(const float2*)(Vb + (size_t)r * HDIM + lane * 2);
            acc.x = fmaf(w, vv.x, acc.x);
            acc.y = fmaf(w, vv.y, acc.y);
        }
        #pragma unroll 8
        for (int kk = 0; kk < 32; kk++) {
            const int r = __shfl_sync(0xffffffffu, r_hi, kk);
            const float w = __shfl_sync(0xffffffffu, w_hi, kk);
            const float2 vv = *(const float2*)(Vb + (size_t)r * HDIM + lane * 2);
            acc.x = fmaf(w, vv.x, acc.x);
            acc.y = fmaf(w, vv.y, acc.y);
        }

        // Write bf16 hi/lo directly in out-proj A layout [b, s, h*64+d]
        const size_t off = ((size_t)(b * SS + s)) * DD + h * HDIM + lane * 2;
        __nv_bfloat16 h0 = __float2bfloat16(acc.x);
        __nv_bfloat16 h1 = __float2bfloat16(acc.y);
        *(__nv_bfloat162*)&gat_hi[off] = __halves2bfloat162(h0, h1);
        __nv_bfloat16 l0 = __float2bfloat16(acc.x - __bfloat162float(h0));
        __nv_bfloat16 l1 = __float2bfloat16(acc.y - __bfloat162float(h1));
        *(__nv_bfloat162*)&gat_lo[off] = __halves2bfloat162(l0, l1);
    }
}

// ---------------------------------------------------------------------------
extern "C" void kernel_launch(void* const* d_in, const int* in_sizes, int n_in,
                              void* d_out, int out_size)
{
    const float* x      = (const float*)d_in[0];
    const float* Wqkv   = (const float*)d_in[1];
    const float* bqkv   = (const float*)d_in[2];
    const float* Wout   = (const float*)d_in[3];
    const float* bout   = (const float*)d_in[4];
    const int*   routes = (const int*)d_in[5];
    float* out = (float*)d_out;

    // Resolve device-global scratch addresses
    __nv_bfloat16 *xh, *xl, *w1h, *w1l, *w2h, *w2l, *ath, *atl;
    cudaGetSymbolAddress((void**)&xh,  gx_hi);
    cudaGetSymbolAddress((void**)&xl,  gx_lo);
    cudaGetSymbolAddress((void**)&w1h, gw1_hi);
    cudaGetSymbolAddress((void**)&w1l, gw1_lo);
    cudaGetSymbolAddress((void**)&w2h, gw2_hi);
    cudaGetSymbolAddress((void**)&w2l, gw2_lo);
    cudaGetSymbolAddress((void**)&ath, gat_hi);
    cudaGetSymbolAddress((void**)&atl, gat_lo);

    constexpr int SMEM_BYTES = 128 * 132 * 4;  // 67584 (union of tiles + staging)
    cudaFuncSetAttribute(gemm_bf16<0>, cudaFuncAttributeMaxDynamicSharedMemorySize, SMEM_BYTES);
    cudaFuncSetAttribute(gemm_bf16<1>, cudaFuncAttributeMaxDynamicSharedMemorySize, SMEM_BYTES);

    // 1) Split-precision conversion of x, Wqkv, Wout
    {
        int n4 = (BB * SS * DD) / 4;
        cvt_k<<<(n4 + 255) / 256, 256>>>((const float4*)x, (__nv_bfloat162*)xh, (__nv_bfloat162*)xl, n4);
        n4 = (DD * 3 * DD) / 4;
        cvt_k<<<(n4 + 255) / 256, 256>>>((const float4*)Wqkv, (__nv_bfloat162*)w1h, (__nv_bfloat162*)w1l, n4);
        n4 = (DD * DD) / 4;
        cvt_k<<<(n4 + 255) / 256, 256>>>((const float4*)Wout, (__nv_bfloat162*)w2h, (__nv_bfloat162*)w2l, n4);
    }

    // 2) QKV GEMM: [4096,512]@[512,1536] + head-scatter epilogue
    gemm_bf16<1><<<dim3(3 * DD / 128, (BB * SS) / 128), 256, SMEM_BYTES>>>(
        xh, xl, w1h, w1l, bqkv, nullptr, BB * SS, 3 * DD, DD);

    // 3) Routed attention (writes bf16 hi/lo attention output)
    attn_k<<<BB * HH * (SS / 32), 256>>>(routes);

    // 4) Out projection: [4096,512]@[512,512]
    gemm_bf16<0><<<dim3(DD / 128, (BB * SS) / 128), 256, SMEM_BYTES>>>(
        ath, atl, w2h, w2l, bout, out, BB * SS, DD, DD);
}

// round 3
// speedup vs baseline: 2.3120x; 2.3120x over previous
#include <cuda_runtime.h>
#include <cuda_bf16.h>
#include <mma.h>

using namespace nvcuda;

#define BB 2
#define SS 2048
#define DD 512
#define HH 8
#define HDIM 64
#define KROUTE 64

// ---------------------------------------------------------------------------
// Scratch (device globals; no allocation allowed)
// ---------------------------------------------------------------------------
__device__ float g_q[BB * HH * SS * HDIM];
__device__ float g_k[BB * HH * SS * HDIM];
__device__ float g_v[BB * HH * SS * HDIM];

__device__ __nv_bfloat16 gx_hi[BB * SS * DD];
__device__ __nv_bfloat16 gx_lo[BB * SS * DD];
__device__ __nv_bfloat16 gw1_hi[DD * 3 * DD];
__device__ __nv_bfloat16 gw1_lo[DD * 3 * DD];
__device__ __nv_bfloat16 gw2_hi[DD * DD];
__device__ __nv_bfloat16 gw2_lo[DD * DD];
__device__ __nv_bfloat16 gat_hi[BB * SS * DD];
__device__ __nv_bfloat16 gat_lo[BB * SS * DD];

// ---------------------------------------------------------------------------
__device__ __forceinline__ void cp16(void* d, const void* s)
{
    unsigned ds = (unsigned)__cvta_generic_to_shared(d);
    asm volatile("cp.async.cg.shared.global [%0], [%1], 16;" :: "r"(ds), "l"(s));
}
__device__ __forceinline__ void cp_commit()
{
    asm volatile("cp.async.commit_group;");
}

// ---------------------------------------------------------------------------
// fp32 -> bf16 hi/lo split conversion (vectorized float4)
// ---------------------------------------------------------------------------
__global__ __launch_bounds__(256) void cvt_k(
    const float4* __restrict__ src,
    __nv_bfloat162* __restrict__ hi,
    __nv_bfloat162* __restrict__ lo, int n4)
{
    int i = blockIdx.x * 256 + threadIdx.x;
    if (i >= n4) return;
    float4 v = src[i];
    __nv_bfloat16 h0 = __float2bfloat16(v.x);
    __nv_bfloat16 h1 = __float2bfloat16(v.y);
    __nv_bfloat16 h2 = __float2bfloat16(v.z);
    __nv_bfloat16 h3 = __float2bfloat16(v.w);
    hi[2 * i + 0] = __halves2bfloat162(h0, h1);
    hi[2 * i + 1] = __halves2bfloat162(h2, h3);
    __nv_bfloat16 l0 = __float2bfloat16(v.x - __bfloat162float(h0));
    __nv_bfloat16 l1 = __float2bfloat16(v.y - __bfloat162float(h1));
    __nv_bfloat16 l2 = __float2bfloat16(v.z - __bfloat162float(h2));
    __nv_bfloat16 l3 = __float2bfloat16(v.w - __bfloat162float(h3));
    lo[2 * i + 0] = __halves2bfloat162(l0, l1);
    lo[2 * i + 1] = __halves2bfloat162(l2, l3);
}

// ---------------------------------------------------------------------------
// Tensor-core GEMM, bf16 hi/lo x3 split, 128x128x32 tile, 2-stage cp.async
// double buffering, 2 CTAs/SM. 8 warps: 4(m) x 2(n); warp tile 32x64.
// ---------------------------------------------------------------------------
template <int MODE>
__global__ __launch_bounds__(256, 2) void gemm_bf16(
    const __nv_bfloat16* __restrict__ Ahi, const __nv_bfloat16* __restrict__ Alo,
    const __nv_bfloat16* __restrict__ Bhi, const __nv_bfloat16* __restrict__ Blo,
    const float* __restrict__ bias, float* __restrict__ C,
    int M, int N, int Kd)
{
    extern __shared__ __align__(16) char smem[];
    constexpr int BM = 128, BN = 128, BK = 32;
    constexpr int LDA = BK + 8;    // 40
    constexpr int LDB = BN + 8;    // 136
    constexpr int LDS_ = BN + 4;   // 132 (epilogue staging, floats)
    constexpr int A_SZ = BM * LDA;                 // 5120 bf16
    constexpr int B_SZ = BK * LDB;                 // 4352 bf16
    constexpr int STG  = 2 * A_SZ + 2 * B_SZ;      // elems per stage

    __nv_bfloat16* base = (__nv_bfloat16*)smem;
    float* stagef = (float*)smem;   // union, reused after k-loop

    const int tid = threadIdx.x;
    const int wid = tid >> 5;
    const int wm = wid & 3;
    const int wn = wid >> 2;

    const size_t aBase = (size_t)blockIdx.y * BM * Kd;
    const int nBase = blockIdx.x * BN;
    const int nK = Kd / BK;

    wmma::fragment<wmma::accumulator, 16, 16, 16, float> acc[2][4];
    #pragma unroll
    for (int mi = 0; mi < 2; mi++)
        #pragma unroll
        for (int ni = 0; ni < 4; ni++) wmma::fill_fragment(acc[mi][ni], 0.0f);

    // async tile prefetch into stage st
    auto prefetch = [&](int ks, int st) {
        const int k0 = ks * BK;
        __nv_bfloat16* sAh = base + st * STG;
        __nv_bfloat16* sAl = sAh + A_SZ;
        __nv_bfloat16* sBh = sAl + A_SZ;
        __nv_bfloat16* sBl = sBh + B_SZ;
        #pragma unroll
        for (int i = 0; i < 2; i++) {
            const int c = tid + 256 * i;
            const int rA = c >> 2, cA = (c & 3) * 8;
            const size_t aoff = aBase + (size_t)rA * Kd + k0 + cA;
            cp16(&sAh[rA * LDA + cA], Ahi + aoff);
            cp16(&sAl[rA * LDA + cA], Alo + aoff);
            const int rB = c >> 4, cB = (c & 15) * 8;
            const size_t boff = (size_t)(k0 + rB) * N + nBase + cB;
            cp16(&sBh[rB * LDB + cB], Bhi + boff);
            cp16(&sBl[rB * LDB + cB], Blo + boff);
        }
        cp_commit();
    };

    prefetch(0, 0);

    for (int ks = 0; ks < nK; ks++) {
        if (ks + 1 < nK) {
            prefetch(ks + 1, (ks + 1) & 1);
            asm volatile("cp.async.wait_group 1;");
        } else {
            asm volatile("cp.async.wait_group 0;");
        }
        __syncthreads();

        const int st = ks & 1;
        const __nv_bfloat16* sAh = base + st * STG;
        const __nv_bfloat16* sAl = sAh + A_SZ;
        const __nv_bfloat16* sBh = sAl + A_SZ;
        const __nv_bfloat16* sBl = sBh + B_SZ;

        #pragma unroll
        for (int kk = 0; kk < BK; kk += 16) {
            wmma::fragment<wmma::matrix_a, 16, 16, 16, __nv_bfloat16, wmma::row_major> ah[2], al[2];
            #pragma unroll
            for (int mi = 0; mi < 2; mi++) {
                wmma::load_matrix_sync(ah[mi], sAh + (wm * 32 + mi * 16) * LDA + kk, LDA);
                wmma::load_matrix_sync(al[mi], sAl + (wm * 32 + mi * 16) * LDA + kk, LDA);
            }
            #pragma unroll
            for (int ni = 0; ni < 4; ni++) {
                wmma::fragment<wmma::matrix_b, 16, 16, 16, __nv_bfloat16, wmma::row_major> bh, bl;
                wmma::load_matrix_sync(bh, sBh + kk * LDB + wn * 64 + ni * 16, LDB);
                wmma::load_matrix_sync(bl, sBl + kk * LDB + wn * 64 + ni * 16, LDB);
                #pragma unroll
                for (int mi = 0; mi < 2; mi++) {
                    wmma::mma_sync(acc[mi][ni], ah[mi], bh, acc[mi][ni]);
                    wmma::mma_sync(acc[mi][ni], ah[mi], bl, acc[mi][ni]);
                    wmma::mma_sync(acc[mi][ni], al[mi], bh, acc[mi][ni]);
                }
            }
        }
        __syncthreads();
    }

    // Epilogue in two 64-row halves (staging fits inside pipeline smem)
    #pragma unroll
    for (int half = 0; half < 2; half++) {
        if ((wm >> 1) == half) {
            #pragma unroll
            for (int mi = 0; mi < 2; mi++)
                #pragma unroll
                for (int ni = 0; ni < 4; ni++)
                    wmma::store_matrix_sync(
                        stagef + ((wm & 1) * 32 + mi * 16) * LDS_ + wn * 64 + ni * 16,
                        acc[mi][ni], LDS_, wmma::mem_row_major);
        }
        __syncthreads();
        #pragma unroll 4
        for (int i = 0; i < (64 * BN) / 256; i++) {
            const int flat = i * 256 + tid;
            const int r = flat >> 7;
            const int c = flat & 127;
            const int n = nBase + c;
            const float v = stagef[r * LDS_ + c] + __ldg(&bias[n]);
            const int m = blockIdx.y * BM + half * 64 + r;
            if (MODE == 0) {
                C[(size_t)m * N + n] = v;
            } else {
                const int b = m >> 11;
                const int s = m & 2047;
                const int c3 = n >> 9;
                const int h = (n >> 6) & 7;
                const int d = n & 63;
                float* dst = (c3 == 0) ? g_q : (c3 == 1) ? g_k : g_v;
                dst[(((size_t)b * HH + h) * SS + s) * HDIM + d] = v;
            }
        }
        __syncthreads();
    }
}

// ---------------------------------------------------------------------------
// Routed attention v3. One warp per query. 8-lane groups each own one route
// per iteration (4 routes/iter): coalesced 2x LDG.128 per lane-group covering
// the 256B K row, 3-level xor reduce within the group, 1 select shuffle.
// ---------------------------------------------------------------------------
__global__ __launch_bounds__(256) void attn_k(const int* __restrict__ routes)
{
    const unsigned FULL = 0xffffffffu;
    const int lane = threadIdx.x & 31;
    const int warp = threadIdx.x >> 5;
    const int chunks = SS / 32;
    const int bh = blockIdx.x / chunks;
    const int sc = blockIdx.x % chunks;
    const int b = bh >> 3, h = bh & 7;
    const int sub = lane & 7;     // 8-float slice of the 64-dim row
    const int grp = lane >> 3;    // 0..3: route group

    const float* Qb = g_q + (size_t)bh * SS * HDIM;
    const float* Kb = g_k + (size_t)bh * SS * HDIM;
    const float* Vb = g_v + (size_t)bh * SS * HDIM;

    #pragma unroll 1
    for (int qi = 0; qi < 4; qi++) {
        const int s = sc * 32 + warp * 4 + qi;

        const float4* qp = (const float4*)(Qb + (size_t)s * HDIM + sub * 8);
        const float4 qa = qp[0], qb4 = qp[1];

        const int r_lo = routes[s * KROUTE + lane];
        const int r_hi = routes[s * KROUTE + 32 + lane];

        float slo = 0.f, shi = 0.f;
        #pragma unroll
        for (int t = 0; t < 16; t++) {
            const int kk31 = (t * 4 + grp) & 31;
            const int r = __shfl_sync(FULL, (t < 8) ? r_lo : r_hi, kk31);
            const float4* kp = (const float4*)(Kb + (size_t)r * HDIM + sub * 8);
            const float4 ka = kp[0], kb4 = kp[1];
            float p = ka.x * qa.x;
            p = fmaf(ka.y, qa.y, p);
            p = fmaf(ka.z, qa.z, p);
            p = fmaf(ka.w, qa.w, p);
            p = fmaf(kb4.x, qb4.x, p);
            p = fmaf(kb4.y, qb4.y, p);
            p = fmaf(kb4.z, qb4.z, p);
            p = fmaf(kb4.w, qb4.w, p);
            p += __shfl_xor_sync(FULL, p, 1);
            p += __shfl_xor_sync(FULL, p, 2);
            p += __shfl_xor_sync(FULL, p, 4);
            const float v = __shfl_sync(FULL, p, (lane & 3) * 8);
            if ((lane >> 2) == t)     slo = v;
            if ((lane >> 2) + 8 == t) shi = v;
        }
        slo *= 0.125f;
        shi *= 0.125f;

        // softmax over 64 scores (2/lane)
        float mx = fmaxf(slo, shi);
        #pragma unroll
        for (int o = 16; o; o >>= 1) mx = fmaxf(mx, __shfl_xor_sync(FULL, mx, o));
        const float e_lo = __expf(slo - mx);
        const float e_hi = __expf(shi - mx);
        float sum = e_lo + e_hi;
        #pragma unroll
        for (int o = 16; o; o >>= 1) sum += __shfl_xor_sync(FULL, sum, o);
        const float inv = __fdividef(1.f, sum);
        const float w_lo = e_lo * inv, w_hi = e_hi * inv;

        // AV: 4 routes/iter, lane accumulates its 8-dim slice for its group
        float4 aa = make_float4(0.f, 0.f, 0.f, 0.f);
        float4 ab = make_float4(0.f, 0.f, 0.f, 0.f);
        #pragma unroll
        for (int t = 0; t < 16; t++) {
            const int kk31 = (t * 4 + grp) & 31;
            const int r = __shfl_sync(FULL, (t < 8) ? r_lo : r_hi, kk31);
            const float w = __shfl_sync(FULL, (t < 8) ? w_lo : w_hi, kk31);
            const float4* vp = (const float4*)(Vb + (size_t)r * HDIM + sub * 8);
            const float4 va = vp[0], vb4 = vp[1];
            aa.x = fmaf(w, va.x, aa.x);
            aa.y = fmaf(w, va.y, aa.y);
            aa.z = fmaf(w, va.z, aa.z);
            aa.w = fmaf(w, va.w, aa.w);
            ab.x = fmaf(w, vb4.x, ab.x);
            ab.y = fmaf(w, vb4.y, ab.y);
            ab.z = fmaf(w, vb4.z, ab.z);
            ab.w = fmaf(w, vb4.w, ab.w);
        }
        // reduce across the 4 groups (lanes with equal sub)
        #pragma unroll
        for (int o = 8; o <= 16; o <<= 1) {
            aa.x += __shfl_xor_sync(FULL, aa.x, o);
            aa.y += __shfl_xor_sync(FULL, aa.y, o);
            aa.z += __shfl_xor_sync(FULL, aa.z, o);
            aa.w += __shfl_xor_sync(FULL, aa.w, o);
            ab.x += __shfl_xor_sync(FULL, ab.x, o);
            ab.y += __shfl_xor_sync(FULL, ab.y, o);
            ab.z += __shfl_xor_sync(FULL, ab.z, o);
            ab.w += __shfl_xor_sync(FULL, ab.w, o);
        }

        if (lane < 8) {
            const size_t off = ((size_t)(b * SS + s)) * DD + h * HDIM + sub * 8;
            float f[8] = {aa.x, aa.y, aa.z, aa.w, ab.x, ab.y, ab.z, ab.w};
            __nv_bfloat162 hp[4], lp[4];
            #pragma unroll
            for (int j = 0; j < 4; j++) {
                __nv_bfloat16 h0 = __float2bfloat16(f[2 * j]);
                __nv_bfloat16 h1 = __float2bfloat16(f[2 * j + 1]);
                hp[j] = __halves2bfloat162(h0, h1);
                __nv_bfloat16 l0 = __float2bfloat16(f[2 * j] - __bfloat162float(h0));
                __nv_bfloat16 l1 = __float2bfloat16(f[2 * j + 1] - __bfloat162float(h1));
                lp[j] = __halves2bfloat162(l0, l1);
            }
            *(uint4*)&gat_hi[off] = *(uint4*)hp;
            *(uint4*)&gat_lo[off] = *(uint4*)lp;
        }
    }
}

// ---------------------------------------------------------------------------
extern "C" void kernel_launch(void* const* d_in, const int* in_sizes, int n_in,
                              void* d_out, int out_size)
{
    const float* x      = (const float*)d_in[0];
    const float* Wqkv   = (const float*)d_in[1];
    const float* bqkv   = (const float*)d_in[2];
    const float* Wout   = (const float*)d_in[3];
    const float* bout   = (const float*)d_in[4];
    const int*   routes = (const int*)d_in[5];
    float* out = (float*)d_out;

    __nv_bfloat16 *xh, *xl, *w1h, *w1l, *w2h, *w2l, *ath, *atl;
    cudaGetSymbolAddress((void**)&xh,  gx_hi);
    cudaGetSymbolAddress((void**)&xl,  gx_lo);
    cudaGetSymbolAddress((void**)&w1h, gw1_hi);
    cudaGetSymbolAddress((void**)&w1l, gw1_lo);
    cudaGetSymbolAddress((void**)&w2h, gw2_hi);
    cudaGetSymbolAddress((void**)&w2l, gw2_lo);
    cudaGetSymbolAddress((void**)&ath, gat_hi);
    cudaGetSymbolAddress((void**)&atl, gat_lo);

    // smem: 2 stages x (2 x 128*40 + 2 x 32*136) bf16 = 75,776 bytes
    constexpr int SMEM_BYTES = 2 * (2 * 128 * 40 + 2 * 32 * 136) * 2;
    cudaFuncSetAttribute(gemm_bf16<0>, cudaFuncAttributeMaxDynamicSharedMemorySize, SMEM_BYTES);
    cudaFuncSetAttribute(gemm_bf16<1>, cudaFuncAttributeMaxDynamicSharedMemorySize, SMEM_BYTES);

    // 1) split-precision conversions
    {
        int n4 = (BB * SS * DD) / 4;
        cvt_k<<<(n4 + 255) / 256, 256>>>((const float4*)x, (__nv_bfloat162*)xh, (__nv_bfloat162*)xl, n4);
        n4 = (DD * 3 * DD) / 4;
        cvt_k<<<(n4 + 255) / 256, 256>>>((const float4*)Wqkv, (__nv_bfloat162*)w1h, (__nv_bfloat162*)w1l, n4);
        n4 = (DD * DD) / 4;
        cvt_k<<<(n4 + 255) / 256, 256>>>((const float4*)Wout, (__nv_bfloat162*)w2h, (__nv_bfloat162*)w2l, n4);
    }

    // 2) QKV GEMM + head-scatter epilogue
    gemm_bf16<1><<<dim3(3 * DD / 128, (BB * SS) / 128), 256, SMEM_BYTES>>>(
        xh, xl, w1h, w1l, bqkv, nullptr, BB * SS, 3 * DD, DD);

    // 3) routed attention
    attn_k<<<BB * HH * (SS / 32), 256>>>(routes);

    // 4) out projection
    gemm_bf16<0><<<dim3(DD / 128, (BB * SS) / 128), 256, SMEM_BYTES>>>(
        ath, atl, w2h, w2l, bout, out, BB * SS, DD, DD);
}

// round 4
// speedup vs baseline: 2.4324x; 1.0521x over previous
#include <cuda_runtime.h>
#include <cuda_bf16.h>
#include <mma.h>

using namespace nvcuda;

#define BB 2
#define SS 2048
#define DD 512
#define HH 8
#define HDIM 64
#define KROUTE 64

// ---------------------------------------------------------------------------
// Scratch (device globals; no allocation allowed)
// ---------------------------------------------------------------------------
__device__ float g_q[BB * HH * SS * HDIM];
__device__ float g_k[BB * HH * SS * HDIM];
__device__ float g_v[BB * HH * SS * HDIM];

__device__ __nv_bfloat16 gx_hi[BB * SS * DD];
__device__ __nv_bfloat16 gx_lo[BB * SS * DD];
__device__ __nv_bfloat16 gw1_hi[DD * 3 * DD];
__device__ __nv_bfloat16 gw1_lo[DD * 3 * DD];
__device__ __nv_bfloat16 gw2_hi[DD * DD];
__device__ __nv_bfloat16 gw2_lo[DD * DD];
__device__ __nv_bfloat16 gat_hi[BB * SS * DD];
__device__ __nv_bfloat16 gat_lo[BB * SS * DD];

// ---------------------------------------------------------------------------
__device__ __forceinline__ void cp16(void* d, const void* s)
{
    unsigned ds = (unsigned)__cvta_generic_to_shared(d);
    asm volatile("cp.async.cg.shared.global [%0], [%1], 16;" :: "r"(ds), "l"(s));
}

// ---------------------------------------------------------------------------
// fp32 -> bf16 hi/lo split conversion (vectorized float4)
// ---------------------------------------------------------------------------
__global__ __launch_bounds__(256) void cvt_k(
    const float4* __restrict__ src,
    __nv_bfloat162* __restrict__ hi,
    __nv_bfloat162* __restrict__ lo, int n4)
{
    int i = blockIdx.x * 256 + threadIdx.x;
    if (i >= n4) return;
    float4 v = src[i];
    __nv_bfloat16 h0 = __float2bfloat16(v.x);
    __nv_bfloat16 h1 = __float2bfloat16(v.y);
    __nv_bfloat16 h2 = __float2bfloat16(v.z);
    __nv_bfloat16 h3 = __float2bfloat16(v.w);
    hi[2 * i + 0] = __halves2bfloat162(h0, h1);
    hi[2 * i + 1] = __halves2bfloat162(h2, h3);
    __nv_bfloat16 l0 = __float2bfloat16(v.x - __bfloat162float(h0));
    __nv_bfloat16 l1 = __float2bfloat16(v.y - __bfloat162float(h1));
    __nv_bfloat16 l2 = __float2bfloat16(v.z - __bfloat162float(h2));
    __nv_bfloat16 l3 = __float2bfloat16(v.w - __bfloat162float(h3));
    lo[2 * i + 0] = __halves2bfloat162(l0, l1);
    lo[2 * i + 1] = __halves2bfloat162(l2, l3);
}

// ---------------------------------------------------------------------------
// Tensor-core GEMM, bf16 hi/lo x3 split, 128x128x32 tile, 3-stage cp.async
// pipeline, 2 CTAs/SM. 8 warps: 4(m) x 2(n); warp tile 32x64.
// ---------------------------------------------------------------------------
template <int MODE>
__global__ __launch_bounds__(256, 2) void gemm_bf16(
    const __nv_bfloat16* __restrict__ Ahi, const __nv_bfloat16* __restrict__ Alo,
    const __nv_bfloat16* __restrict__ Bhi, const __nv_bfloat16* __restrict__ Blo,
    const float* __restrict__ bias, float* __restrict__ C,
    int M, int N, int Kd)
{
    extern __shared__ __align__(16) char smem[];
    constexpr int BM = 128, BN = 128, BK = 32;
    constexpr int LDA = BK + 8;    // 40
    constexpr int LDB = BN + 8;    // 136
    constexpr int LDS_ = BN + 4;   // 132 (epilogue staging, floats)
    constexpr int A_SZ = BM * LDA;                 // 5120 bf16
    constexpr int B_SZ = BK * LDB;                 // 4352 bf16
    constexpr int STG  = 2 * A_SZ + 2 * B_SZ;      // 18944 elems per stage

    __nv_bfloat16* base = (__nv_bfloat16*)smem;
    float* stagef = (float*)smem;   // union, reused after k-loop

    const int tid = threadIdx.x;
    const int wid = tid >> 5;
    const int wm = wid & 3;
    const int wn = wid >> 2;

    const size_t aBase = (size_t)blockIdx.y * BM * Kd;
    const int nBase = blockIdx.x * BN;
    const int nK = Kd / BK;

    wmma::fragment<wmma::accumulator, 16, 16, 16, float> acc[2][4];
    #pragma unroll
    for (int mi = 0; mi < 2; mi++)
        #pragma unroll
        for (int ni = 0; ni < 4; ni++) wmma::fill_fragment(acc[mi][ni], 0.0f);

    auto prefetch = [&](int ks, int st) {
        const int k0 = ks * BK;
        __nv_bfloat16* sAh = base + st * STG;
        __nv_bfloat16* sAl = sAh + A_SZ;
        __nv_bfloat16* sBh = sAl + A_SZ;
        __nv_bfloat16* sBl = sBh + B_SZ;
        #pragma unroll
        for (int i = 0; i < 2; i++) {
            const int c = tid + 256 * i;
            const int rA = c >> 2, cA = (c & 3) * 8;
            const size_t aoff = aBase + (size_t)rA * Kd + k0 + cA;
            cp16(&sAh[rA * LDA + cA], Ahi + aoff);
            cp16(&sAl[rA * LDA + cA], Alo + aoff);
            const int rB = c >> 4, cB = (c & 15) * 8;
            const size_t boff = (size_t)(k0 + rB) * N + nBase + cB;
            cp16(&sBh[rB * LDB + cB], Bhi + boff);
            cp16(&sBl[rB * LDB + cB], Blo + boff);
        }
        asm volatile("cp.async.commit_group;");
    };

    prefetch(0, 0);
    if (nK > 1) prefetch(1, 1);

    for (int ks = 0; ks < nK; ks++) {
        if (ks + 2 < nK) {
            prefetch(ks + 2, (ks + 2) % 3);
            asm volatile("cp.async.wait_group 2;");
        } else if (ks + 1 < nK) {
            asm volatile("cp.async.wait_group 1;");
        } else {
            asm volatile("cp.async.wait_group 0;");
        }
        __syncthreads();

        const int st = ks % 3;
        const __nv_bfloat16* sAh = base + st * STG;
        const __nv_bfloat16* sAl = sAh + A_SZ;
        const __nv_bfloat16* sBh = sAl + A_SZ;
        const __nv_bfloat16* sBl = sBh + B_SZ;

        #pragma unroll
        for (int kk = 0; kk < BK; kk += 16) {
            wmma::fragment<wmma::matrix_a, 16, 16, 16, __nv_bfloat16, wmma::row_major> ah[2], al[2];
            #pragma unroll
            for (int mi = 0; mi < 2; mi++) {
                wmma::load_matrix_sync(ah[mi], sAh + (wm * 32 + mi * 16) * LDA + kk, LDA);
                wmma::load_matrix_sync(al[mi], sAl + (wm * 32 + mi * 16) * LDA + kk, LDA);
            }
            #pragma unroll
            for (int ni = 0; ni < 4; ni++) {
                wmma::fragment<wmma::matrix_b, 16, 16, 16, __nv_bfloat16, wmma::row_major> bh, bl;
                wmma::load_matrix_sync(bh, sBh + kk * LDB + wn * 64 + ni * 16, LDB);
                wmma::load_matrix_sync(bl, sBl + kk * LDB + wn * 64 + ni * 16, LDB);
                #pragma unroll
                for (int mi = 0; mi < 2; mi++) {
                    wmma::mma_sync(acc[mi][ni], ah[mi], bh, acc[mi][ni]);
                    wmma::mma_sync(acc[mi][ni], ah[mi], bl, acc[mi][ni]);
                    wmma::mma_sync(acc[mi][ni], al[mi], bh, acc[mi][ni]);
                }
            }
        }
        __syncthreads();
    }

    // Epilogue in two 64-row halves
    #pragma unroll
    for (int half = 0; half < 2; half++) {
        if ((wm >> 1) == half) {
            #pragma unroll
            for (int mi = 0; mi < 2; mi++)
                #pragma unroll
                for (int ni = 0; ni < 4; ni++)
                    wmma::store_matrix_sync(
                        stagef + ((wm & 1) * 32 + mi * 16) * LDS_ + wn * 64 + ni * 16,
                        acc[mi][ni], LDS_, wmma::mem_row_major);
        }
        __syncthreads();
        #pragma unroll 4
        for (int i = 0; i < (64 * BN) / 256; i++) {
            const int flat = i * 256 + tid;
            const int r = flat >> 7;
            const int c = flat & 127;
            const int n = nBase + c;
            const float v = stagef[r * LDS_ + c] + __ldg(&bias[n]);
            const int m = blockIdx.y * BM + half * 64 + r;
            if (MODE == 0) {
                C[(size_t)m * N + n] = v;
            } else {
                const int b = m >> 11;
                const int s = m & 2047;
                const int c3 = n >> 9;
                const int h = (n >> 6) & 7;
                const int d = n & 63;
                float* dst = (c3 == 0) ? g_q : (c3 == 1) ? g_k : g_v;
                dst[(((size_t)b * HH + h) * SS + s) * HDIM + d] = v;
            }
        }
        __syncthreads();
    }
}

// ---------------------------------------------------------------------------
// Routed attention v4: 2 queries per loop iteration (doubled MLP). 8-lane
// groups own one route per query per iter; 3-level xor reduce + 1 select.
// ---------------------------------------------------------------------------
__global__ __launch_bounds__(256) void attn_k(const int* __restrict__ routes)
{
    const unsigned FULL = 0xffffffffu;
    const int lane = threadIdx.x & 31;
    const int warp = threadIdx.x >> 5;
    const int chunks = SS / 32;
    const int bh = blockIdx.x / chunks;
    const int sc = blockIdx.x % chunks;
    const int b = bh >> 3, h = bh & 7;
    const int sub = lane & 7;     // 8-float slice of the 64-dim row
    const int grp = lane >> 3;    // 0..3: route group

    const float* Qb = g_q + (size_t)bh * SS * HDIM;
    const float* Kb = g_k + (size_t)bh * SS * HDIM;
    const float* Vb = g_v + (size_t)bh * SS * HDIM;

    #pragma unroll 1
    for (int qp = 0; qp < 2; qp++) {
        const int s0 = sc * 32 + warp * 4 + qp * 2;
        const int s1 = s0 + 1;

        const float4* qp0 = (const float4*)(Qb + (size_t)s0 * HDIM + sub * 8);
        const float4 q0a = qp0[0], q0b = qp0[1];
        const float4* qp1 = (const float4*)(Qb + (size_t)s1 * HDIM + sub * 8);
        const float4 q1a = qp1[0], q1b = qp1[1];

        const int r_lo0 = routes[s0 * KROUTE + lane];
        const int r_hi0 = routes[s0 * KROUTE + 32 + lane];
        const int r_lo1 = routes[s1 * KROUTE + lane];
        const int r_hi1 = routes[s1 * KROUTE + 32 + lane];

        float slo0 = 0.f, shi0 = 0.f, slo1 = 0.f, shi1 = 0.f;
        #pragma unroll
        for (int t = 0; t < 16; t++) {
            const int kk31 = (t * 4 + grp) & 31;
            const int r0 = __shfl_sync(FULL, (t < 8) ? r_lo0 : r_hi0, kk31);
            const int r1 = __shfl_sync(FULL, (t < 8) ? r_lo1 : r_hi1, kk31);
            const float4* kp0 = (const float4*)(Kb + (size_t)r0 * HDIM + sub * 8);
            const float4* kp1 = (const float4*)(Kb + (size_t)r1 * HDIM + sub * 8);
            const float4 k0a = kp0[0], k0b = kp0[1];
            const float4 k1a = kp1[0], k1b = kp1[1];

            float p0 = k0a.x * q0a.x;
            p0 = fmaf(k0a.y, q0a.y, p0);
            p0 = fmaf(k0a.z, q0a.z, p0);
            p0 = fmaf(k0a.w, q0a.w, p0);
            p0 = fmaf(k0b.x, q0b.x, p0);
            p0 = fmaf(k0b.y, q0b.y, p0);
            p0 = fmaf(k0b.z, q0b.z, p0);
            p0 = fmaf(k0b.w, q0b.w, p0);
            float p1 = k1a.x * q1a.x;
            p1 = fmaf(k1a.y, q1a.y, p1);
            p1 = fmaf(k1a.z, q1a.z, p1);
            p1 = fmaf(k1a.w, q1a.w, p1);
            p1 = fmaf(k1b.x, q1b.x, p1);
            p1 = fmaf(k1b.y, q1b.y, p1);
            p1 = fmaf(k1b.z, q1b.z, p1);
            p1 = fmaf(k1b.w, q1b.w, p1);

            p0 += __shfl_xor_sync(FULL, p0, 1);
            p1 += __shfl_xor_sync(FULL, p1, 1);
            p0 += __shfl_xor_sync(FULL, p0, 2);
            p1 += __shfl_xor_sync(FULL, p1, 2);
            p0 += __shfl_xor_sync(FULL, p0, 4);
            p1 += __shfl_xor_sync(FULL, p1, 4);
            const float v0 = __shfl_sync(FULL, p0, (lane & 3) * 8);
            const float v1 = __shfl_sync(FULL, p1, (lane & 3) * 8);
            if ((lane >> 2) == t)     { slo0 = v0; slo1 = v1; }
            if ((lane >> 2) + 8 == t) { shi0 = v0; shi1 = v1; }
        }
        slo0 *= 0.125f; shi0 *= 0.125f;
        slo1 *= 0.125f; shi1 *= 0.125f;

        // softmax over 64 scores (2/lane) for both queries
        float mx0 = fmaxf(slo0, shi0);
        float mx1 = fmaxf(slo1, shi1);
        #pragma unroll
        for (int o = 16; o; o >>= 1) {
            mx0 = fmaxf(mx0, __shfl_xor_sync(FULL, mx0, o));
            mx1 = fmaxf(mx1, __shfl_xor_sync(FULL, mx1, o));
        }
        const float elo0 = __expf(slo0 - mx0), ehi0 = __expf(shi0 - mx0);
        const float elo1 = __expf(slo1 - mx1), ehi1 = __expf(shi1 - mx1);
        float sum0 = elo0 + ehi0;
        float sum1 = elo1 + ehi1;
        #pragma unroll
        for (int o = 16; o; o >>= 1) {
            sum0 += __shfl_xor_sync(FULL, sum0, o);
            sum1 += __shfl_xor_sync(FULL, sum1, o);
        }
        const float inv0 = __fdividef(1.f, sum0);
        const float inv1 = __fdividef(1.f, sum1);
        const float wlo0 = elo0 * inv0, whi0 = ehi0 * inv0;
        const float wlo1 = elo1 * inv1, whi1 = ehi1 * inv1;

        // AV: 4 routes/iter per query, both queries interleaved
        float4 a0a = make_float4(0.f, 0.f, 0.f, 0.f);
        float4 a0b = make_float4(0.f, 0.f, 0.f, 0.f);
        float4 a1a = make_float4(0.f, 0.f, 0.f, 0.f);
        float4 a1b = make_float4(0.f, 0.f, 0.f, 0.f);
        #pragma unroll
        for (int t = 0; t < 16; t++) {
            const int kk31 = (t * 4 + grp) & 31;
            const int r0 = __shfl_sync(FULL, (t < 8) ? r_lo0 : r_hi0, kk31);
            const float w0 = __shfl_sync(FULL, (t < 8) ? wlo0 : whi0, kk31);
            const int r1 = __shfl_sync(FULL, (t < 8) ? r_lo1 : r_hi1, kk31);
            const float w1 = __shfl_sync(FULL, (t < 8) ? wlo1 : whi1, kk31);
            const float4* vp0 = (const float4*)(Vb + (size_t)r0 * HDIM + sub * 8);
            const float4* vp1 = (const float4*)(Vb + (size_t)r1 * HDIM + sub * 8);
            const float4 v0a = vp0[0], v0b = vp0[1];
            const float4 v1a = vp1[0], v1b = vp1[1];
            a0a.x = fmaf(w0, v0a.x, a0a.x);
            a0a.y = fmaf(w0, v0a.y, a0a.y);
            a0a.z = fmaf(w0, v0a.z, a0a.z);
            a0a.w = fmaf(w0, v0a.w, a0a.w);
            a0b.x = fmaf(w0, v0b.x, a0b.x);
            a0b.y = fmaf(w0, v0b.y, a0b.y);
            a0b.z = fmaf(w0, v0b.z, a0b.z);
            a0b.w = fmaf(w0, v0b.w, a0b.w);
            a1a.x = fmaf(w1, v1a.x, a1a.x);
            a1a.y = fmaf(w1, v1a.y, a1a.y);
            a1a.z = fmaf(w1, v1a.z, a1a.z);
            a1a.w = fmaf(w1, v1a.w, a1a.w);
            a1b.x = fmaf(w1, v1b.x, a1b.x);
            a1b.y = fmaf(w1, v1b.y, a1b.y);
            a1b.z = fmaf(w1, v1b.z, a1b.z);
            a1b.w = fmaf(w1, v1b.w, a1b.w);
        }
        // reduce across the 4 groups (lanes with equal sub)
        #pragma unroll
        for (int o = 8; o <= 16; o <<= 1) {
            a0a.x += __shfl_xor_sync(FULL, a0a.x, o);
            a0a.y += __shfl_xor_sync(FULL, a0a.y, o);
            a0a.z += __shfl_xor_sync(FULL, a0a.z, o);
            a0a.w += __shfl_xor_sync(FULL, a0a.w, o);
            a0b.x += __shfl_xor_sync(FULL, a0b.x, o);
            a0b.y += __shfl_xor_sync(FULL, a0b.y, o);
            a0b.z += __shfl_xor_sync(FULL, a0b.z, o);
            a0b.w += __shfl_xor_sync(FULL, a0b.w, o);
            a1a.x += __shfl_xor_sync(FULL, a1a.x, o);
            a1a.y += __shfl_xor_sync(FULL, a1a.y, o);
            a1a.z += __shfl_xor_sync(FULL, a1a.z, o);
            a1a.w += __shfl_xor_sync(FULL, a1a.w, o);
            a1b.x += __shfl_xor_sync(FULL, a1b.x, o);
            a1b.y += __shfl_xor_sync(FULL, a1b.y, o);
            a1b.z += __shfl_xor_sync(FULL, a1b.z, o);
            a1b.w += __shfl_xor_sync(FULL, a1b.w, o);
        }

        if (lane < 8) {
            #pragma unroll
            for (int qq = 0; qq < 2; qq++) {
                const int s = s0 + qq;
                const float4 xa = qq ? a1a : a0a;
                const float4 xb = qq ? a1b : a0b;
                const size_t off = ((size_t)(b * SS + s)) * DD + h * HDIM + sub * 8;
                float f[8] = {xa.x, xa.y, xa.z, xa.w, xb.x, xb.y, xb.z, xb.w};
                __nv_bfloat162 hp[4], lp[4];
                #pragma unroll
                for (int j = 0; j < 4; j++) {
                    __nv_bfloat16 h0 = __float2bfloat16(f[2 * j]);
                    __nv_bfloat16 h1 = __float2bfloat16(f[2 * j + 1]);
                    hp[j] = __halves2bfloat162(h0, h1);
                    __nv_bfloat16 l0 = __float2bfloat16(f[2 * j] - __bfloat162float(h0));
                    __nv_bfloat16 l1 = __float2bfloat16(f[2 * j + 1] - __bfloat162float(h1));
                    lp[j] = __halves2bfloat162(l0, l1);
                }
                *(uint4*)&gat_hi[off] = *(uint4*)hp;
                *(uint4*)&gat_lo[off] = *(uint4*)lp;
            }
        }
    }
}

// ---------------------------------------------------------------------------
extern "C" void kernel_launch(void* const* d_in, const int* in_sizes, int n_in,
                              void* d_out, int out_size)
{
    const float* x      = (const float*)d_in[0];
    const float* Wqkv   = (const float*)d_in[1];
    const float* bqkv   = (const float*)d_in[2];
    const float* Wout   = (const float*)d_in[3];
    const float* bout   = (const float*)d_in[4];
    const int*   routes = (const int*)d_in[5];
    float* out = (float*)d_out;

    __nv_bfloat16 *xh, *xl, *w1h, *w1l, *w2h, *w2l, *ath, *atl;
    cudaGetSymbolAddress((void**)&xh,  gx_hi);
    cudaGetSymbolAddress((void**)&xl,  gx_lo);
    cudaGetSymbolAddress((void**)&w1h, gw1_hi);
    cudaGetSymbolAddress((void**)&w1l, gw1_lo);
    cudaGetSymbolAddress((void**)&w2h, gw2_hi);
    cudaGetSymbolAddress((void**)&w2l, gw2_lo);
    cudaGetSymbolAddress((void**)&ath, gat_hi);
    cudaGetSymbolAddress((void**)&atl, gat_lo);

    // smem: 3 stages x (2 x 128*40 + 2 x 32*136) bf16 = 113,664 bytes
    constexpr int SMEM_BYTES = 3 * (2 * 128 * 40 + 2 * 32 * 136) * 2;
    cudaFuncSetAttribute(gemm_bf16<0>, cudaFuncAttributeMaxDynamicSharedMemorySize, SMEM_BYTES);
    cudaFuncSetAttribute(gemm_bf16<1>, cudaFuncAttributeMaxDynamicSharedMemorySize, SMEM_BYTES);

    // 1) split-precision conversions
    {
        int n4 = (BB * SS * DD) / 4;
        cvt_k<<<(n4 + 255) / 256, 256>>>((const float4*)x, (__nv_bfloat162*)xh, (__nv_bfloat162*)xl, n4);
        n4 = (DD * 3 * DD) / 4;
        cvt_k<<<(n4 + 255) / 256, 256>>>((const float4*)Wqkv, (__nv_bfloat162*)w1h, (__nv_bfloat162*)w1l, n4);
        n4 = (DD * DD) / 4;
        cvt_k<<<(n4 + 255) / 256, 256>>>((const float4*)Wout, (__nv_bfloat162*)w2h, (__nv_bfloat162*)w2l, n4);
    }

    // 2) QKV GEMM + head-scatter epilogue
    gemm_bf16<1><<<dim3(3 * DD / 128, (BB * SS) / 128), 256, SMEM_BYTES>>>(
        xh, xl, w1h, w1l, bqkv, nullptr, BB * SS, 3 * DD, DD);

    // 3) routed attention
    attn_k<<<BB * HH * (SS / 32), 256>>>(routes);

    // 4) out projection
    gemm_bf16<0><<<dim3(DD / 128, (BB * SS) / 128), 256, SMEM_BYTES>>>(
        ath, atl, w2h, w2l, bout, out, BB * SS, DD, DD);
}